// round 5
// baseline (speedup 1.0000x reference)
#include <cuda_runtime.h>

#define BM 128
#define BN 128
#define BK 16
#define NT 256

// Fused TensorProductRescale:
//   region 0            : out0 (N=256, K=384)  A = [x0*y0 | d],      W = [SQK0*w000 ; SQK0*IS3*w110]
//   region i (i0=0..2)  : out1[:,:,i0] (N=128, K=512)
//                         A = [x0*y1_i | x1_i*y0 | cr_i], W = [SQK1*w011 ; SQK1*w101 ; SQK1*IS2*w111]
__global__ void __launch_bounds__(NT, 2)
tpr_kernel(const float* __restrict__ x, const float* __restrict__ y,
           const float* __restrict__ w000, const float* __restrict__ w110,
           const float* __restrict__ w011, const float* __restrict__ w101,
           const float* __restrict__ w111, const float* __restrict__ b0,
           float* __restrict__ out, int B)
{
    const float SQK0 = 0.05103103630798288f;   // 1/sqrt(384)
    const float SQK1 = 0.04419417382415922f;   // 1/sqrt(512)
    const float IS3  = 0.57735026918962584f;   // 1/sqrt(3)
    const float IS2  = 0.70710678118654752f;   // 1/sqrt(2)

    __shared__ float As[BK][BM + 1];   // +1 pad: conflict-free k-strided writes
    __shared__ float Ws[BK][BN];
    __shared__ float ys[BM][4];

    const int job  = blockIdx.x;           // 0,1 -> region0 colblock; 2,3,4 -> region 1..3
    const int row0 = blockIdx.y * BM;
    const int tid  = threadIdx.x;
    const int tx   = tid & 15;             // col group (8 cols each)
    const int ty   = tid >> 4;             // row group (8 strided rows each)
    const int nb   = tx * 8;

    int region, cb;
    if (job < 2) { region = 0; cb = job; } else { region = job - 1; cb = 0; }
    const int i0 = region - 1;             // only meaningful when region > 0
    const int j1 = (i0 + 1) % 3;
    const int j2 = (i0 + 2) % 3;

    // load y tile
    for (int i = tid; i < BM * 4; i += NT) {
        int m = i >> 2, c = i & 3;
        int r = row0 + m;
        ys[m][c] = (r < B) ? y[(size_t)r * 4 + c] : 0.0f;
    }

    float acc[8][8];
    #pragma unroll
    for (int r = 0; r < 8; r++)
        #pragma unroll
        for (int c = 0; c < 8; c++) acc[r][c] = 0.0f;

    const int KT  = (region == 0) ? 24 : 32;   // K/BK
    const int fm  = tid >> 1;                  // feature row handled by this thread
    const int fkb = (tid & 1) * 8;             // feature k sub-block (0 or 8)
    const int frow = row0 + fm;
    const float* xr = x + (size_t)frow * 640;

    __syncthreads();   // ys ready

    for (int kt = 0; kt < KT; kt++) {
        const int k0 = kt * BK;

        // ---- stage weight tile (scales folded) ----
        #pragma unroll
        for (int r = 0; r < 2; r++) {
            int idx = tid + r * NT;        // float4 index within 16x128 tile
            int kw  = idx >> 5;            // 0..15
            int col = (idx & 31) * 4;
            int kg  = k0 + kw;
            const float* src; float s;
            if (region == 0) {
                if (kg < 256) { src = w000 + (size_t)kg * 256 + cb * 128 + col;        s = SQK0; }
                else          { src = w110 + (size_t)(kg - 256) * 256 + cb * 128 + col; s = SQK0 * IS3; }
            } else {
                if (kg < 256)      { src = w011 + (size_t)kg * 128 + col;         s = SQK1; }
                else if (kg < 384) { src = w101 + (size_t)(kg - 256) * 128 + col; s = SQK1; }
                else               { src = w111 + (size_t)(kg - 384) * 128 + col; s = SQK1 * IS2; }
            }
            float4 v = *(const float4*)src;
            v.x *= s; v.y *= s; v.z *= s; v.w *= s;
            *(float4*)&Ws[kw][col] = v;
        }

        // ---- stage feature tile (computed on the fly) ----
        float f[8];
        if (frow < B) {
            float yv0 = ys[fm][0], yv1 = ys[fm][1], yv2 = ys[fm][2], yv3 = ys[fm][3];
            if (k0 < 256) {
                float sc = (region == 0) ? yv0 : ys[fm][1 + i0];
                const float4* p = (const float4*)(xr + k0 + fkb);
                float4 a0 = p[0], a1 = p[1];
                f[0] = a0.x * sc; f[1] = a0.y * sc; f[2] = a0.z * sc; f[3] = a0.w * sc;
                f[4] = a1.x * sc; f[5] = a1.y * sc; f[6] = a1.z * sc; f[7] = a1.w * sc;
            } else {
                int u0, mode;                   // 0: d, 1: x1_i*y0, 2: cross
                if (region == 0)   { u0 = k0 - 256 + fkb; mode = 0; }
                else if (k0 < 384) { u0 = k0 - 256 + fkb; mode = 1; }
                else               { u0 = k0 - 384 + fkb; mode = 2; }
                const float4* p = (const float4*)(xr + 256 + 3 * u0);
                float v[24];
                #pragma unroll
                for (int q = 0; q < 6; q++) *(float4*)&v[4 * q] = p[q];
                #pragma unroll
                for (int jj = 0; jj < 8; jj++) {
                    float e0 = v[3 * jj], e1 = v[3 * jj + 1], e2 = v[3 * jj + 2];
                    if (mode == 0) {
                        f[jj] = e0 * yv1 + e1 * yv2 + e2 * yv3;          // d[u]
                    } else if (mode == 1) {
                        float xi = (i0 == 0) ? e0 : ((i0 == 1) ? e1 : e2);
                        f[jj] = xi * yv0;                                 // x1_i * y0
                    } else {
                        // cr_i = x1_{j1} * y1_{j2} - x1_{j2} * y1_{j1}
                        float xa = (j1 == 0) ? e0 : ((j1 == 1) ? e1 : e2);
                        float xb = (j2 == 0) ? e0 : ((j2 == 1) ? e1 : e2);
                        float ya = (j2 == 0) ? yv1 : ((j2 == 1) ? yv2 : yv3);
                        float yb = (j1 == 0) ? yv1 : ((j1 == 1) ? yv2 : yv3);
                        f[jj] = xa * ya - xb * yb;
                    }
                }
            }
        } else {
            #pragma unroll
            for (int jj = 0; jj < 8; jj++) f[jj] = 0.0f;
        }
        #pragma unroll
        for (int jj = 0; jj < 8; jj++) As[fkb + jj][fm] = f[jj];

        __syncthreads();

        // ---- compute ----
        #pragma unroll
        for (int k = 0; k < BK; k++) {
            float a[8];
            #pragma unroll
            for (int r = 0; r < 8; r++) a[r] = As[k][ty + 16 * r];
            float4 w0 = *(const float4*)&Ws[k][nb];
            float4 w1 = *(const float4*)&Ws[k][nb + 4];
            float w[8] = {w0.x, w0.y, w0.z, w0.w, w1.x, w1.y, w1.z, w1.w};
            #pragma unroll
            for (int r = 0; r < 8; r++)
                #pragma unroll
                for (int c = 0; c < 8; c++)
                    acc[r][c] = fmaf(a[r], w[c], acc[r][c]);
        }

        __syncthreads();
    }

    // ---- epilogue ----
    if (region == 0) {
        float4 bv0 = *(const float4*)&b0[cb * 128 + nb];
        float4 bv1 = *(const float4*)&b0[cb * 128 + nb + 4];
        #pragma unroll
        for (int r = 0; r < 8; r++) {
            int row = row0 + ty + 16 * r;
            if (row < B) {
                float* o = out + (size_t)row * 640 + cb * 128 + nb;
                float4 s0 = make_float4(acc[r][0] + bv0.x, acc[r][1] + bv0.y,
                                        acc[r][2] + bv0.z, acc[r][3] + bv0.w);
                float4 s1 = make_float4(acc[r][4] + bv1.x, acc[r][5] + bv1.y,
                                        acc[r][6] + bv1.z, acc[r][7] + bv1.w);
                *(float4*)o       = s0;
                *(float4*)(o + 4) = s1;
            }
        }
    } else {
        #pragma unroll
        for (int r = 0; r < 8; r++) {
            int row = row0 + ty + 16 * r;
            if (row < B) {
                float* o = out + (size_t)row * 640 + 256 + i0;
                #pragma unroll
                for (int c = 0; c < 8; c++)
                    o[(nb + c) * 3] = acc[r][c];   // out1 layout: 256 + w*3 + i
            }
        }
    }
}

extern "C" void kernel_launch(void* const* d_in, const int* in_sizes, int n_in,
                              void* d_out, int out_size)
{
    const float* x    = (const float*)d_in[0];
    const float* y    = (const float*)d_in[1];
    const float* w000 = (const float*)d_in[2];
    const float* w110 = (const float*)d_in[3];
    const float* w011 = (const float*)d_in[4];
    const float* w101 = (const float*)d_in[5];
    const float* w111 = (const float*)d_in[6];
    const float* b0   = (const float*)d_in[7];
    int B = in_sizes[0] / 640;

    dim3 grid(5, (B + BM - 1) / BM, 1);
    tpr_kernel<<<grid, NT>>>(x, y, w000, w110, w011, w101, w111, b0,
                             (float*)d_out, B);
}

// round 7
// speedup vs baseline: 1.9612x; 1.9612x over previous
#include <cuda_runtime.h>
#include <cstdint>

#define NT 256
#define BM 128
#define BK 16
#define AS_STRIDE 20     // [m][k] stride -> conflict-free A frag loads
#define WS_STRIDE 136    // [k][n] stride -> conflict-free B frag loads

__device__ __forceinline__ uint32_t f2tf32(float x) {
    uint32_t u;
    asm("cvt.rna.tf32.f32 %0, %1;" : "=r"(u) : "f"(x));
    return u;
}

__device__ __forceinline__ void mma_tf32(float* d, const uint32_t* a, const uint32_t* b) {
    asm volatile(
        "mma.sync.aligned.m16n8k8.row.col.f32.tf32.tf32.f32 "
        "{%0,%1,%2,%3}, {%4,%5,%6,%7}, {%8,%9}, {%0,%1,%2,%3};"
        : "+f"(d[0]), "+f"(d[1]), "+f"(d[2]), "+f"(d[3])
        : "r"(a[0]), "r"(a[1]), "r"(a[2]), "r"(a[3]), "r"(b[0]), "r"(b[1]));
}

// Fused TensorProductRescale via tf32 mma.sync:
//   job 0/1 : out0 colblock cb (N=128, K=384)  A=[x0*y0 | d]      W=[SQK0*w000 ; SQK0/sqrt3*w110]
//   job 2-4 : out1 component i0 (N=128, K=512) A=[x0*y1_i|x1_i*y0|cr_i] W=[SQK1*w011;SQK1*w101;SQK1/sqrt2*w111]
__global__ void __launch_bounds__(NT, 2)
tpr_kernel(const float* __restrict__ x, const float* __restrict__ y,
           const float* __restrict__ w000, const float* __restrict__ w110,
           const float* __restrict__ w011, const float* __restrict__ w101,
           const float* __restrict__ w111, const float* __restrict__ b0,
           float* __restrict__ out, int B)
{
    const float SQK0 = 0.05103103630798288f;   // 1/sqrt(384)
    const float SQK1 = 0.04419417382415922f;   // 1/sqrt(512)
    const float IS3  = 0.57735026918962584f;   // 1/sqrt(3)
    const float IS2  = 0.70710678118654752f;   // 1/sqrt(2)

    __shared__ uint32_t As[2][BM * AS_STRIDE];     // tf32 bits, [m][k]
    __shared__ uint32_t Ws[2][BK * WS_STRIDE];     // tf32 bits, [k][n]
    __shared__ float bias[128];

    const int job  = blockIdx.x;
    const int row0 = blockIdx.y * BM;
    const int tid  = threadIdx.x;
    const int wid  = tid >> 5;
    const int lane = tid & 31;
    const int qr   = lane >> 2;   // 0..7
    const int qc   = lane & 3;    // 0..3
    const int wm   = wid & 3;     // warp m index (32 rows)
    const int wn   = wid >> 2;    // warp n index (64 cols)

    int region, cb;
    if (job < 2) { region = 0; cb = job; } else { region = job - 1; cb = 0; }
    const int i0 = region - 1;
    const int j1 = (i0 + 1) % 3;
    const int j2 = (i0 + 2) % 3;
    const int KT = (region == 0) ? 24 : 32;

    // ---- per-thread staging role ----
    const int fm   = tid >> 1;            // feature row
    const int klo  = (tid & 1) * 8;       // k sub-block within BK
    const int frow = row0 + fm;
    const bool valid = frow < B;
    const float* xr = x + (size_t)frow * 640;
    float yv[4] = {0.f, 0.f, 0.f, 0.f};
    if (valid) {
        float4 t = *(const float4*)(y + (size_t)frow * 4);
        yv[0] = t.x; yv[1] = t.y; yv[2] = t.z; yv[3] = t.w;
    }

    if (region == 0 && tid < 128) bias[tid] = b0[cb * 128 + tid];

    // W staging role: 2 float4 rows per thread
    // idx = tid + r*NT over 512 float4s: kw = idx>>5, col = (idx&31)*4

    float acc[2][8][4];
    #pragma unroll
    for (int mi = 0; mi < 2; mi++)
        #pragma unroll
        for (int ni = 0; ni < 8; ni++)
            #pragma unroll
            for (int c = 0; c < 4; c++) acc[mi][ni][c] = 0.f;

    // ---------- staging helpers (inlined via lambdas) ----------
    auto load_feat = [&](int kt, float* f) {
        const int kg0 = kt * BK + klo;
        if (!valid) {
            #pragma unroll
            for (int j = 0; j < 8; j++) f[j] = 0.f;
        } else if (kg0 < 256) {
            float s = (region == 0) ? yv[0] : yv[1 + i0];
            const float4* p = (const float4*)(xr + kg0);
            float4 a0 = p[0], a1 = p[1];
            f[0] = a0.x * s; f[1] = a0.y * s; f[2] = a0.z * s; f[3] = a0.w * s;
            f[4] = a1.x * s; f[5] = a1.y * s; f[6] = a1.z * s; f[7] = a1.w * s;
        } else {
            int u0, mode;
            if (region == 0)    { u0 = kg0 - 256; mode = 0; }
            else if (kg0 < 384) { u0 = kg0 - 256; mode = 1; }
            else                { u0 = kg0 - 384; mode = 2; }
            const float4* p = (const float4*)(xr + 256 + 3 * u0);
            float v[24];
            #pragma unroll
            for (int q = 0; q < 6; q++) *(float4*)&v[4 * q] = p[q];
            #pragma unroll
            for (int j = 0; j < 8; j++) {
                float e0 = v[3*j], e1 = v[3*j+1], e2 = v[3*j+2];
                if (mode == 0) {
                    f[j] = e0 * yv[1] + e1 * yv[2] + e2 * yv[3];
                } else if (mode == 1) {
                    float xi = (i0 == 0) ? e0 : ((i0 == 1) ? e1 : e2);
                    f[j] = xi * yv[0];
                } else {
                    float xa = (j1 == 0) ? e0 : ((j1 == 1) ? e1 : e2);
                    float xb = (j2 == 0) ? e0 : ((j2 == 1) ? e1 : e2);
                    f[j] = xa * yv[1 + j2] - xb * yv[1 + j1];
                }
            }
        }
    };

    auto load_w = [&](int kt, float4* w) {
        const int k0 = kt * BK;
        #pragma unroll
        for (int r = 0; r < 2; r++) {
            int idx = tid + r * NT;
            int kw  = idx >> 5;
            int col = (idx & 31) * 4;
            int kg  = k0 + kw;
            const float* src; float s;
            if (region == 0) {
                if (kg < 256) { src = w000 + (size_t)kg * 256 + cb * 128 + col;         s = SQK0; }
                else          { src = w110 + (size_t)(kg - 256) * 256 + cb * 128 + col; s = SQK0 * IS3; }
            } else {
                if (kg < 256)      { src = w011 + (size_t)kg * 128 + col;         s = SQK1; }
                else if (kg < 384) { src = w101 + (size_t)(kg - 256) * 128 + col; s = SQK1; }
                else               { src = w111 + (size_t)(kg - 384) * 128 + col; s = SQK1 * IS2; }
            }
            float4 v = *(const float4*)src;
            v.x *= s; v.y *= s; v.z *= s; v.w *= s;
            w[r] = v;
        }
    };

    auto store_tile = [&](int b, const float* f, const float4* w) {
        uint32_t* ap = &As[b][fm * AS_STRIDE + klo];
        #pragma unroll
        for (int j = 0; j < 8; j++) ap[j] = f2tf32(f[j]);
        #pragma unroll
        for (int r = 0; r < 2; r++) {
            int idx = tid + r * NT;
            int kw  = idx >> 5;
            int col = (idx & 31) * 4;
            uint32_t* wp = &Ws[b][kw * WS_STRIDE + col];
            wp[0] = f2tf32(w[r].x); wp[1] = f2tf32(w[r].y);
            wp[2] = f2tf32(w[r].z); wp[3] = f2tf32(w[r].w);
        }
    };

    // ---------- prologue: stage tile 0 ----------
    float  fcur[8];
    float4 wcur[2];
    load_feat(0, fcur);
    load_w(0, wcur);
    store_tile(0, fcur, wcur);
    __syncthreads();

    // ---------- main loop ----------
    for (int kt = 0; kt < KT; kt++) {
        const int b = kt & 1;
        const bool more = (kt + 1 < KT);
        if (more) { load_feat(kt + 1, fcur); load_w(kt + 1, wcur); }

        const uint32_t* Ab = As[b];
        const uint32_t* Wb = Ws[b];
        #pragma unroll
        for (int ks = 0; ks < 2; ks++) {
            const int k = ks * 8;
            uint32_t a[2][4];
            #pragma unroll
            for (int mi = 0; mi < 2; mi++) {
                const uint32_t* p = &Ab[(wm * 32 + mi * 16 + qr) * AS_STRIDE + k + qc];
                a[mi][0] = p[0];
                a[mi][1] = p[8 * AS_STRIDE];
                a[mi][2] = p[4];
                a[mi][3] = p[8 * AS_STRIDE + 4];
            }
            #pragma unroll
            for (int ni = 0; ni < 8; ni++) {
                uint32_t bb[2];
                const uint32_t* q = &Wb[(k + qc) * WS_STRIDE + wn * 64 + ni * 8 + qr];
                bb[0] = q[0];
                bb[1] = q[4 * WS_STRIDE];
                mma_tf32(acc[0][ni], a[0], bb);
                mma_tf32(acc[1][ni], a[1], bb);
            }
        }

        if (more) store_tile(b ^ 1, fcur, wcur);
        __syncthreads();
    }

    // ---------- epilogue ----------
    #pragma unroll
    for (int mi = 0; mi < 2; mi++) {
        #pragma unroll
        for (int half = 0; half < 2; half++) {       // c0/c1 vs c2/c3 (rows +8)
            int row = row0 + wm * 32 + mi * 16 + qr + half * 8;
            if (row >= B) continue;
            if (region == 0) {
                float* o = out + (size_t)row * 640 + cb * 128;
                #pragma unroll
                for (int ni = 0; ni < 8; ni++) {
                    int col = wn * 64 + ni * 8 + qc * 2;
                    float2 v = make_float2(acc[mi][ni][half * 2]     + bias[col],
                                           acc[mi][ni][half * 2 + 1] + bias[col + 1]);
                    *(float2*)(o + col) = v;
                }
            } else {
                float* o = out + (size_t)row * 640 + 256 + i0;
                #pragma unroll
                for (int ni = 0; ni < 8; ni++) {
                    int col = wn * 64 + ni * 8 + qc * 2;
                    o[col * 3]       = acc[mi][ni][half * 2];
                    o[(col + 1) * 3] = acc[mi][ni][half * 2 + 1];
                }
            }
        }
    }
}

extern "C" void kernel_launch(void* const* d_in, const int* in_sizes, int n_in,
                              void* d_out, int out_size)
{
    const float* x    = (const float*)d_in[0];
    const float* y    = (const float*)d_in[1];
    const float* w000 = (const float*)d_in[2];
    const float* w110 = (const float*)d_in[3];
    const float* w011 = (const float*)d_in[4];
    const float* w101 = (const float*)d_in[5];
    const float* w111 = (const float*)d_in[6];
    const float* b0   = (const float*)d_in[7];
    int B = in_sizes[0] / 640;

    dim3 grid(5, (B + BM - 1) / BM);
    tpr_kernel<<<grid, NT>>>(x, y, w000, w110, w011, w101, w111, b0,
                             (float*)d_out, B);
}

// round 8
// speedup vs baseline: 2.3041x; 1.1748x over previous
#include <cuda_runtime.h>
#include <cstdint>

#define NT 256
#define BM 128
#define BK 32
#define AS_STRIDE 36     // [m][k] stride: frag-load bank = 4*qr+qc -> conflict-free
#define WS_STRIDE 136    // [k][n] stride: frag-load bank = 8*qc+qr -> conflict-free
#define A_TILE (BM * AS_STRIDE)              // 4608 u32
#define W_TILE (BK * WS_STRIDE)              // 4352 u32
#define OFF_W  (2 * A_TILE)
#define OFF_BIAS (2 * A_TILE + 2 * W_TILE)
#define SMEM_BYTES ((2 * A_TILE + 2 * W_TILE + 128) * 4)   // 72192 B

// Pre-scaled, tf32-rounded weights, [job][k][n=128]:
// job 0/1: region0 cb=0/1, K=384 ; job 2-4: region 1..3, K=512
__device__ uint32_t g_wt[294912];

__device__ __forceinline__ uint32_t f2tf32(float x) {
    uint32_t u;
    asm("cvt.rna.tf32.f32 %0, %1;" : "=r"(u) : "f"(x));
    return u;
}
__device__ __forceinline__ uint32_t smem_u32(const void* p) {
    uint32_t a;
    asm("{ .reg .u64 t; cvta.to.shared.u64 t, %1; cvt.u32.u64 %0, t; }" : "=r"(a) : "l"(p));
    return a;
}
__device__ __forceinline__ void cp16(uint32_t dst, const void* src) {
    asm volatile("cp.async.ca.shared.global [%0], [%1], 16;" :: "r"(dst), "l"(src));
}
__device__ __forceinline__ void mma_tf32(float* d, const uint32_t* a, const uint32_t* b) {
    asm volatile(
        "mma.sync.aligned.m16n8k8.row.col.f32.tf32.tf32.f32 "
        "{%0,%1,%2,%3}, {%4,%5,%6,%7}, {%8,%9}, {%0,%1,%2,%3};"
        : "+f"(d[0]), "+f"(d[1]), "+f"(d[2]), "+f"(d[3])
        : "r"(a[0]), "r"(a[1]), "r"(a[2]), "r"(a[3]), "r"(b[0]), "r"(b[1]));
}

// ---------------- weight prep: fold scales + tf32 round + transpose ----------------
__global__ void prep_wt(const float* __restrict__ w000, const float* __restrict__ w110,
                        const float* __restrict__ w011, const float* __restrict__ w101,
                        const float* __restrict__ w111)
{
    const float SQK0 = 0.05103103630798288f;
    const float SQK1 = 0.04419417382415922f;
    const float IS3  = 0.57735026918962584f;
    const float IS2  = 0.70710678118654752f;

    int idx = blockIdx.x * 256 + threadIdx.x;
    if (idx >= 294912) return;
    int job, rem;
    if (idx < 98304) { job = idx / 49152; rem = idx % 49152; }
    else             { int t = idx - 98304; job = 2 + t / 65536; rem = t % 65536; }
    int k = rem >> 7, n = rem & 127;
    float v;
    if (job < 2) {
        int cb = job;
        if (k < 256) v = SQK0 * w000[k * 256 + cb * 128 + n];
        else         v = SQK0 * IS3 * w110[(k - 256) * 256 + cb * 128 + n];
    } else {
        if (k < 256)      v = SQK1 * w011[k * 128 + n];
        else if (k < 384) v = SQK1 * w101[(k - 256) * 128 + n];
        else              v = SQK1 * IS2 * w111[(k - 384) * 128 + n];
    }
    g_wt[idx] = f2tf32(v);
}

// ---------------- main kernel ----------------
__global__ void __launch_bounds__(NT, 2)
tpr_kernel(const float* __restrict__ x, const float* __restrict__ y,
           const float* __restrict__ b0, float* __restrict__ out, int B)
{
    extern __shared__ uint32_t sm[];
    const uint32_t sb = smem_u32(sm);

    const int job  = blockIdx.x;
    const int row0 = blockIdx.y * BM;
    const int tid  = threadIdx.x;
    const int wid  = tid >> 5;
    const int lane = tid & 31;
    const int qr   = lane >> 2;
    const int qc   = lane & 3;
    const int wm   = wid & 3;     // warp m (32 rows)
    const int wn   = wid >> 2;    // warp n (64 cols)

    int region, cb;
    if (job < 2) { region = 0; cb = job; } else { region = job - 1; cb = 0; }
    const int i0 = region - 1;
    const int j1 = (i0 + 1) % 3;
    const int j2 = (i0 + 2) % 3;
    const int KT = (region == 0) ? 12 : 16;
    const uint32_t* wbase = g_wt + ((job < 2) ? job * 49152 : 98304 + (job - 2) * 65536);

    // staging role: one row per thread-pair, 16 k per thread
    const int fm   = tid >> 1;
    const int klo  = (tid & 1) * 16;
    const int frow = row0 + fm;
    const bool valid = frow < B;
    const float* xr = x + (size_t)frow * 640;
    float yv[4] = {0.f, 0.f, 0.f, 0.f};
    if (valid) {
        float4 t = *(const float4*)(y + (size_t)frow * 4);
        yv[0] = t.x; yv[1] = t.y; yv[2] = t.z; yv[3] = t.w;
    }
    if (region == 0 && tid < 128)
        ((float*)(sm + OFF_BIAS))[tid] = b0[cb * 128 + tid];

    float acc[2][8][4];
    #pragma unroll
    for (int mi = 0; mi < 2; mi++)
        #pragma unroll
        for (int ni = 0; ni < 8; ni++)
            #pragma unroll
            for (int c = 0; c < 4; c++) acc[mi][ni][c] = 0.f;

    // ---- W tile: cp.async straight copy from pre-scaled g_wt ----
    auto issueW = [&](int kt, int b) {
        const uint32_t dbase = sb + (OFF_W + b * W_TILE) * 4;
        const uint32_t* src = wbase + (size_t)(kt * BK) * 128;
        #pragma unroll
        for (int i = 0; i < 4; i++) {
            int idx = tid + i * NT;
            int kw = idx >> 5, c16 = idx & 31;
            cp16(dbase + (uint32_t)(kw * WS_STRIDE + c16 * 4) * 4,
                 src + kw * 128 + c16 * 4);
        }
        asm volatile("cp.async.commit_group;" ::: "memory");
    };

    // ---- A tile: gated features, 16 per thread ----
    auto load_feat = [&](int kt, float* f) {
        const int kg0 = kt * BK + klo;
        if (!valid) {
            #pragma unroll
            for (int j = 0; j < 16; j++) f[j] = 0.f;
        } else if (kg0 < 256) {
            float s = (region == 0) ? yv[0] : yv[1 + i0];
            const float4* p = (const float4*)(xr + kg0);
            #pragma unroll
            for (int q = 0; q < 4; q++) {
                float4 a = p[q];
                f[4*q+0] = a.x * s; f[4*q+1] = a.y * s;
                f[4*q+2] = a.z * s; f[4*q+3] = a.w * s;
            }
        } else {
            int u0, mode;
            if (region == 0)    { u0 = kg0 - 256; mode = 0; }
            else if (kg0 < 384) { u0 = kg0 - 256; mode = 1; }
            else                { u0 = kg0 - 384; mode = 2; }
            const float4* p = (const float4*)(xr + 256 + 3 * u0);
            float v[48];
            #pragma unroll
            for (int q = 0; q < 12; q++) *(float4*)&v[4*q] = p[q];
            #pragma unroll
            for (int j = 0; j < 16; j++) {
                float e0 = v[3*j], e1 = v[3*j+1], e2 = v[3*j+2];
                if (mode == 0) {
                    f[j] = e0 * yv[1] + e1 * yv[2] + e2 * yv[3];
                } else if (mode == 1) {
                    float xi = (i0 == 0) ? e0 : ((i0 == 1) ? e1 : e2);
                    f[j] = xi * yv[0];
                } else {
                    float xa = (j1 == 0) ? e0 : ((j1 == 1) ? e1 : e2);
                    float xb = (j2 == 0) ? e0 : ((j2 == 1) ? e1 : e2);
                    f[j] = xa * yv[1 + j2] - xb * yv[1 + j1];
                }
            }
        }
    };
    auto storeA = [&](int b, const float* f) {
        uint32_t* ap = sm + b * A_TILE + fm * AS_STRIDE + klo;
        #pragma unroll
        for (int c = 0; c < 4; c++) {
            uint4 u = make_uint4(f2tf32(f[4*c]), f2tf32(f[4*c+1]),
                                 f2tf32(f[4*c+2]), f2tf32(f[4*c+3]));
            *(uint4*)(ap + 4*c) = u;
        }
    };

    // ---------- prologue ----------
    float f[16];
    issueW(0, 0);
    load_feat(0, f);
    storeA(0, f);

    // ---------- main loop: 1 barrier / tile, cp.async overlapped ----------
    for (int kt = 0; kt < KT; kt++) {
        const int b = kt & 1;
        asm volatile("cp.async.wait_group 0;" ::: "memory");
        __syncthreads();

        const bool more = (kt + 1 < KT);
        if (more) { issueW(kt + 1, b ^ 1); load_feat(kt + 1, f); }

        const uint32_t* Ab = sm + b * A_TILE;
        const uint32_t* Wb = sm + OFF_W + b * W_TILE;
        #pragma unroll
        for (int ks = 0; ks < 4; ks++) {
            const int k = ks * 8;
            uint32_t a[2][4];
            #pragma unroll
            for (int mi = 0; mi < 2; mi++) {
                const uint32_t* p = &Ab[(wm * 32 + mi * 16 + qr) * AS_STRIDE + k + qc];
                a[mi][0] = p[0];
                a[mi][1] = p[8 * AS_STRIDE];
                a[mi][2] = p[4];
                a[mi][3] = p[8 * AS_STRIDE + 4];
            }
            #pragma unroll
            for (int ni = 0; ni < 8; ni++) {
                uint32_t bb[2];
                const uint32_t* q = &Wb[(k + qc) * WS_STRIDE + wn * 64 + ni * 8 + qr];
                bb[0] = q[0];
                bb[1] = q[4 * WS_STRIDE];
                mma_tf32(acc[0][ni], a[0], bb);
                mma_tf32(acc[1][ni], a[1], bb);
            }
        }

        if (more) storeA(b ^ 1, f);
    }

    // ---------- epilogue ----------
    const float* bias = (const float*)(sm + OFF_BIAS);
    #pragma unroll
    for (int mi = 0; mi < 2; mi++) {
        #pragma unroll
        for (int half = 0; half < 2; half++) {
            int row = row0 + wm * 32 + mi * 16 + qr + half * 8;
            if (row >= B) continue;
            if (region == 0) {
                float* o = out + (size_t)row * 640 + cb * 128;
                #pragma unroll
                for (int ni = 0; ni < 8; ni++) {
                    int col = wn * 64 + ni * 8 + qc * 2;
                    float2 v = make_float2(acc[mi][ni][half * 2]     + bias[col],
                                           acc[mi][ni][half * 2 + 1] + bias[col + 1]);
                    *(float2*)(o + col) = v;
                }
            } else {
                float* o = out + (size_t)row * 640 + 256 + i0;
                #pragma unroll
                for (int ni = 0; ni < 8; ni++) {
                    int col = wn * 64 + ni * 8 + qc * 2;
                    o[col * 3]       = acc[mi][ni][half * 2];
                    o[(col + 1) * 3] = acc[mi][ni][half * 2 + 1];
                }
            }
        }
    }
}

extern "C" void kernel_launch(void* const* d_in, const int* in_sizes, int n_in,
                              void* d_out, int out_size)
{
    const float* x    = (const float*)d_in[0];
    const float* y    = (const float*)d_in[1];
    const float* w000 = (const float*)d_in[2];
    const float* w110 = (const float*)d_in[3];
    const float* w011 = (const float*)d_in[4];
    const float* w101 = (const float*)d_in[5];
    const float* w111 = (const float*)d_in[6];
    const float* b0   = (const float*)d_in[7];
    int B = in_sizes[0] / 640;

    static bool attr_set = false;
    if (!attr_set) {
        cudaFuncSetAttribute(tpr_kernel, cudaFuncAttributeMaxDynamicSharedMemorySize,
                             SMEM_BYTES);
        attr_set = true;
    }

    prep_wt<<<(294912 + 255) / 256, 256>>>(w000, w110, w011, w101, w111);

    dim3 grid(5, (B + BM - 1) / BM);
    tpr_kernel<<<grid, NT, SMEM_BYTES>>>(x, y, b0, (float*)d_out, B);
}

// round 9
// speedup vs baseline: 2.7912x; 1.2114x over previous
#include <cuda_runtime.h>
#include <cuda_fp16.h>
#include <cstdint>

#define NT 256
#define BM 128
#define BK 32                 // K floats per tile -> 16 half2 words
#define KP 16                 // k-pair words per tile
#define AS_STRIDE 20          // u32 stride [m][kp]: banks 20*qr+qc distinct
#define WS_STRIDE 136         // u32 stride [kp][n]: banks 8*qc+qr distinct
#define A_TILE (BM * AS_STRIDE)        // 2560 u32
#define W_TILE (KP * WS_STRIDE)        // 2176 u32
#define OFF_W  (2 * A_TILE)
#define OFF_BIAS (2 * A_TILE + 2 * W_TILE)
#define SMEM_BYTES ((2 * A_TILE + 2 * W_TILE + 128) * 4)   // 38400 B

// Pre-scaled fp16x2-packed weights, [job][kp][n=128] u32:
// job 0/1: region0 cb=0/1 (kp=192) ; job 2-4: region 1..3 (kp=256)
__device__ uint32_t g_wt[147456];

__device__ __forceinline__ uint32_t smem_u32(const void* p) {
    uint32_t a;
    asm("{ .reg .u64 t; cvta.to.shared.u64 t, %1; cvt.u32.u64 %0, t; }" : "=r"(a) : "l"(p));
    return a;
}
__device__ __forceinline__ void cp16(uint32_t dst, const void* src) {
    asm volatile("cp.async.ca.shared.global [%0], [%1], 16;" :: "r"(dst), "l"(src));
}
__device__ __forceinline__ uint32_t pack_h2(float lo, float hi) {
    half2 h = __floats2half2_rn(lo, hi);
    return *(uint32_t*)&h;
}
__device__ __forceinline__ void mma_f16(float* d, const uint32_t* a, const uint32_t* b) {
    asm volatile(
        "mma.sync.aligned.m16n8k16.row.col.f32.f16.f16.f32 "
        "{%0,%1,%2,%3}, {%4,%5,%6,%7}, {%8,%9}, {%0,%1,%2,%3};"
        : "+f"(d[0]), "+f"(d[1]), "+f"(d[2]), "+f"(d[3])
        : "r"(a[0]), "r"(a[1]), "r"(a[2]), "r"(a[3]), "r"(b[0]), "r"(b[1]));
}

// ---------------- weight prep: fold scales + fp16 pack (k-pairs) ----------------
__global__ void prep_wt(const float* __restrict__ w000, const float* __restrict__ w110,
                        const float* __restrict__ w011, const float* __restrict__ w101,
                        const float* __restrict__ w111)
{
    const float SQK0 = 0.05103103630798288f;
    const float SQK1 = 0.04419417382415922f;
    const float IS3  = 0.57735026918962584f;
    const float IS2  = 0.70710678118654752f;

    int idx = blockIdx.x * 256 + threadIdx.x;
    if (idx >= 147456) return;
    int job, rem;
    if (idx < 49152) { job = idx / 24576; rem = idx % 24576; }
    else             { int t = idx - 49152; job = 2 + t / 32768; rem = t % 32768; }
    int kp = rem >> 7, n = rem & 127;

    float w2[2];
    #pragma unroll
    for (int h = 0; h < 2; h++) {
        int k = 2 * kp + h;
        float v;
        if (job < 2) {
            int cb = job;
            if (k < 256) v = SQK0 * w000[k * 256 + cb * 128 + n];
            else         v = SQK0 * IS3 * w110[(k - 256) * 256 + cb * 128 + n];
        } else {
            if (k < 256)      v = SQK1 * w011[k * 128 + n];
            else if (k < 384) v = SQK1 * w101[(k - 256) * 128 + n];
            else              v = SQK1 * IS2 * w111[(k - 384) * 128 + n];
        }
        w2[h] = v;
    }
    g_wt[idx] = pack_h2(w2[0], w2[1]);
}

// ---------------- main kernel ----------------
__global__ void __launch_bounds__(NT, 2)
tpr_kernel(const float* __restrict__ x, const float* __restrict__ y,
           const float* __restrict__ b0, float* __restrict__ out, int B)
{
    extern __shared__ uint32_t sm[];
    const uint32_t sb = smem_u32(sm);

    const int job  = blockIdx.x;
    const int row0 = blockIdx.y * BM;
    const int tid  = threadIdx.x;
    const int wid  = tid >> 5;
    const int lane = tid & 31;
    const int qr   = lane >> 2;
    const int qc   = lane & 3;
    const int wm   = wid & 3;     // warp m (32 rows)
    const int wn   = wid >> 2;    // warp n (64 cols)

    int region, cb;
    if (job < 2) { region = 0; cb = job; } else { region = job - 1; cb = 0; }
    const int i0 = region - 1;
    const int j1 = (i0 + 1) % 3;
    const int j2 = (i0 + 2) % 3;
    const int KT = (region == 0) ? 12 : 16;
    const uint32_t* wbase = g_wt + ((job < 2) ? job * 24576 : 49152 + (job - 2) * 32768);

    // staging role: one row per thread-pair, 16 k (8 words) per thread
    const int fm   = tid >> 1;
    const int klo  = (tid & 1) * 16;       // k offset within BK
    const int kwo  = (tid & 1) * 8;        // word offset within KP
    const int frow = row0 + fm;
    const bool valid = frow < B;
    const float* xr = x + (size_t)frow * 640;
    float yv[4] = {0.f, 0.f, 0.f, 0.f};
    if (valid) {
        float4 t = *(const float4*)(y + (size_t)frow * 4);
        yv[0] = t.x; yv[1] = t.y; yv[2] = t.z; yv[3] = t.w;
    }
    if (region == 0 && tid < 128)
        ((float*)(sm + OFF_BIAS))[tid] = b0[cb * 128 + tid];

    float acc[2][8][4];
    #pragma unroll
    for (int mi = 0; mi < 2; mi++)
        #pragma unroll
        for (int ni = 0; ni < 8; ni++)
            #pragma unroll
            for (int c = 0; c < 4; c++) acc[mi][ni][c] = 0.f;

    // ---- W tile: cp.async straight copy (pre-packed fp16x2) ----
    auto issueW = [&](int kt, int b) {
        const uint32_t dbase = sb + (OFF_W + b * W_TILE) * 4;
        const uint32_t* src = wbase + (size_t)(kt * KP) * 128;
        #pragma unroll
        for (int i = 0; i < 2; i++) {
            int idx = tid + i * NT;        // over 512 16B chunks
            int kw = idx >> 5, c16 = idx & 31;
            cp16(dbase + (uint32_t)(kw * WS_STRIDE + c16 * 4) * 4,
                 src + kw * 128 + c16 * 4);
        }
        asm volatile("cp.async.commit_group;" ::: "memory");
    };

    // ---- A tile: gated features, 16 per thread ----
    auto load_feat = [&](int kt, float* f) {
        const int kg0 = kt * BK + klo;
        if (!valid) {
            #pragma unroll
            for (int j = 0; j < 16; j++) f[j] = 0.f;
        } else if (kg0 < 256) {
            float s = (region == 0) ? yv[0] : yv[1 + i0];
            const float4* p = (const float4*)(xr + kg0);
            #pragma unroll
            for (int q = 0; q < 4; q++) {
                float4 a = p[q];
                f[4*q+0] = a.x * s; f[4*q+1] = a.y * s;
                f[4*q+2] = a.z * s; f[4*q+3] = a.w * s;
            }
        } else {
            int u0, mode;
            if (region == 0)    { u0 = kg0 - 256; mode = 0; }
            else if (kg0 < 384) { u0 = kg0 - 256; mode = 1; }
            else                { u0 = kg0 - 384; mode = 2; }
            const float4* p = (const float4*)(xr + 256 + 3 * u0);
            float v[48];
            #pragma unroll
            for (int q = 0; q < 12; q++) *(float4*)&v[4*q] = p[q];
            #pragma unroll
            for (int j = 0; j < 16; j++) {
                float e0 = v[3*j], e1 = v[3*j+1], e2 = v[3*j+2];
                if (mode == 0) {
                    f[j] = e0 * yv[1] + e1 * yv[2] + e2 * yv[3];
                } else if (mode == 1) {
                    float xi = (i0 == 0) ? e0 : ((i0 == 1) ? e1 : e2);
                    f[j] = xi * yv[0];
                } else {
                    float xa = (j1 == 0) ? e0 : ((j1 == 1) ? e1 : e2);
                    float xb = (j2 == 0) ? e0 : ((j2 == 1) ? e1 : e2);
                    f[j] = xa * yv[1 + j2] - xb * yv[1 + j1];
                }
            }
        }
    };
    auto storeA = [&](int b, const float* f) {
        uint32_t* ap = sm + b * A_TILE + fm * AS_STRIDE + kwo;
        uint4 u0 = make_uint4(pack_h2(f[0], f[1]),  pack_h2(f[2], f[3]),
                              pack_h2(f[4], f[5]),  pack_h2(f[6], f[7]));
        uint4 u1 = make_uint4(pack_h2(f[8], f[9]),  pack_h2(f[10], f[11]),
                              pack_h2(f[12], f[13]), pack_h2(f[14], f[15]));
        *(uint4*)(ap)     = u0;
        *(uint4*)(ap + 4) = u1;
    };

    // ---------- prologue ----------
    float f[16];
    issueW(0, 0);
    load_feat(0, f);
    storeA(0, f);

    // ---------- main loop: 1 barrier / tile, cp.async overlapped ----------
    for (int kt = 0; kt < KT; kt++) {
        const int b = kt & 1;
        asm volatile("cp.async.wait_group 0;" ::: "memory");
        __syncthreads();

        const bool more = (kt + 1 < KT);
        if (more) { issueW(kt + 1, b ^ 1); load_feat(kt + 1, f); }

        const uint32_t* Ab = sm + b * A_TILE;
        const uint32_t* Wb = sm + OFF_W + b * W_TILE;
        #pragma unroll
        for (int ks = 0; ks < 2; ks++) {
            const int base = ks * 8;        // k-pair base (k16 per MMA)
            uint32_t a[2][4];
            #pragma unroll
            for (int mi = 0; mi < 2; mi++) {
                const uint32_t* p = &Ab[(wm * 32 + mi * 16 + qr) * AS_STRIDE + base + qc];
                a[mi][0] = p[0];
                a[mi][1] = p[8 * AS_STRIDE];
                a[mi][2] = p[4];
                a[mi][3] = p[8 * AS_STRIDE + 4];
            }
            #pragma unroll
            for (int ni = 0; ni < 8; ni++) {
                uint32_t bb[2];
                const uint32_t* q = &Wb[(base + qc) * WS_STRIDE + wn * 64 + ni * 8 + qr];
                bb[0] = q[0];
                bb[1] = q[4 * WS_STRIDE];
                mma_f16(acc[0][ni], a[0], bb);
                mma_f16(acc[1][ni], a[1], bb);
            }
        }

        if (more) storeA(b ^ 1, f);
    }

    // ---------- epilogue ----------
    const float* bias = (const float*)(sm + OFF_BIAS);
    #pragma unroll
    for (int mi = 0; mi < 2; mi++) {
        #pragma unroll
        for (int half = 0; half < 2; half++) {
            int row = row0 + wm * 32 + mi * 16 + qr + half * 8;
            if (row >= B) continue;
            if (region == 0) {
                float* o = out + (size_t)row * 640 + cb * 128;
                #pragma unroll
                for (int ni = 0; ni < 8; ni++) {
                    int col = wn * 64 + ni * 8 + qc * 2;
                    float2 v = make_float2(acc[mi][ni][half * 2]     + bias[col],
                                           acc[mi][ni][half * 2 + 1] + bias[col + 1]);
                    *(float2*)(o + col) = v;
                }
            } else {
                float* o = out + (size_t)row * 640 + 256 + i0;
                #pragma unroll
                for (int ni = 0; ni < 8; ni++) {
                    int col = wn * 64 + ni * 8 + qc * 2;
                    o[col * 3]       = acc[mi][ni][half * 2];
                    o[(col + 1) * 3] = acc[mi][ni][half * 2 + 1];
                }
            }
        }
    }
}

extern "C" void kernel_launch(void* const* d_in, const int* in_sizes, int n_in,
                              void* d_out, int out_size)
{
    const float* x    = (const float*)d_in[0];
    const float* y    = (const float*)d_in[1];
    const float* w000 = (const float*)d_in[2];
    const float* w110 = (const float*)d_in[3];
    const float* w011 = (const float*)d_in[4];
    const float* w101 = (const float*)d_in[5];
    const float* w111 = (const float*)d_in[6];
    const float* b0   = (const float*)d_in[7];
    int B = in_sizes[0] / 640;

    prep_wt<<<(147456 + 255) / 256, 256>>>(w000, w110, w011, w101, w111);

    dim3 grid(5, (B + BM - 1) / BM);
    tpr_kernel<<<grid, NT, SMEM_BYTES>>>(x, y, b0, (float*)d_out, B);
}